// round 2
// baseline (speedup 1.0000x reference)
#include <cuda_runtime.h>
#include <cstdint>

#define FULL_MASK 0xFFFFFFFFu

constexpr int B_ = 2048;
constexpr int L_ = 2048;
constexpr int T_ = 8;
constexpr float LOG2E_F = 1.4426950408889634f;
constexpr float LN2_F   = 0.6931471805599453f;

// per-batch log-likelihoods (scratch; device globals allowed, no cudaMalloc)
__device__ float g_llh[B_];

struct ECol { float e0, e1, e2, e3, e4, e5, e6, e7; };

// One recursion step in the scaled-linear domain.
// lane j of each 8-lane group holds a = (scaled) alpha_j and column j of E=exp(trans).
__device__ __forceinline__ void crf_step(
    float em_t, int tag_t, const ECol& E,
    const float* s_trans, int j, bool act,
    float& a, float& num, int& s_prev)
{
    float ex = exp2f(em_t * LOG2E_F);          // exp(em) via single MUFU
    float a0 = __shfl_sync(FULL_MASK, a, 0, 8);
    float a1 = __shfl_sync(FULL_MASK, a, 1, 8);
    float a2 = __shfl_sync(FULL_MASK, a, 2, 8);
    float a3 = __shfl_sync(FULL_MASK, a, 3, 8);
    float a4 = __shfl_sync(FULL_MASK, a, 4, 8);
    float a5 = __shfl_sync(FULL_MASK, a, 5, 8);
    float a6 = __shfl_sync(FULL_MASK, a, 6, 8);
    float a7 = __shfl_sync(FULL_MASK, a, 7, 8);
    int   s_t = (tag_t - 1) & 7;               // masked to stay valid when tag==0 (act=false)
    float emg = __shfl_sync(FULL_MASK, em_t, s_t, 8);  // emission at the gold tag
    float u0 = fmaf(a1, E.e1, a0 * E.e0);
    float u1 = fmaf(a3, E.e3, a2 * E.e2);
    float u2 = fmaf(a5, E.e5, a4 * E.e4);
    float u3 = fmaf(a7, E.e7, a6 * E.e6);
    float s  = (u0 + u1) + (u2 + u3);
    if (act) {
        a = s * ex;
        if (j == 0) num += s_trans[(s_prev << 3) | s_t] + emg;
        s_prev = s_t;
    }
}

// Exact power-of-two renormalization: divide group max down to [1,2),
// accumulate its exponent into c (log2 scale). c stays integer-exact.
__device__ __forceinline__ void crf_renorm(float& a, float& c)
{
    float m = a;
    m = fmaxf(m, __shfl_xor_sync(FULL_MASK, m, 1));
    m = fmaxf(m, __shfl_xor_sync(FULL_MASK, m, 2));
    m = fmaxf(m, __shfl_xor_sync(FULL_MASK, m, 4));
    int eb = __float_as_int(m) & 0x7f800000;
    c += (float)((eb >> 23) - 127);
    a *= __int_as_float(0x7f000000 - eb);      // exact 2^{-e}
}

__global__ __launch_bounds__(64)
void crf_main(const float* __restrict__ em,
              const float* __restrict__ trans,
              const float* __restrict__ startT,
              const float* __restrict__ endT,
              const int*   __restrict__ tags)     // (B, L) int32
{
    __shared__ float s_trans[T_ * T_];
    int tid = threadIdx.x;
    s_trans[tid] = trans[tid];                   // blockDim.x == 64 == T*T
    __syncthreads();

    int lane   = tid & 31;
    int j      = lane & 7;                       // tag index within group
    int warpId = (blockIdx.x * 64 + tid) >> 5;   // global warp id
    int b      = warpId * 4 + (lane >> 3);       // batch handled by this 8-lane group

    // E column j in registers
    ECol E;
    E.e0 = exp2f(s_trans[0 * 8 + j] * LOG2E_F);
    E.e1 = exp2f(s_trans[1 * 8 + j] * LOG2E_F);
    E.e2 = exp2f(s_trans[2 * 8 + j] * LOG2E_F);
    E.e3 = exp2f(s_trans[3 * 8 + j] * LOG2E_F);
    E.e4 = exp2f(s_trans[4 * 8 + j] * LOG2E_F);
    E.e5 = exp2f(s_trans[5 * 8 + j] * LOG2E_F);
    E.e6 = exp2f(s_trans[6 * 8 + j] * LOG2E_F);
    E.e7 = exp2f(s_trans[7 * 8 + j] * LOG2E_F);

    const float* emb = em   + (size_t)b * (L_ * T_) + j;   // this lane's emission column
    const int*   tgb = tags + (size_t)b * L_;              // int32, stride 1

    // t = 0 init
    int   tag0   = tgb[0];
    int   s_prev = tag0 - 1;                     // lengths >= 1024 so tag0 != 0
    float em0    = emb[0];
    float a      = exp2f((startT[j] + em0) * LOG2E_F);
    float c      = 0.0f;                         // log2-domain scale accumulator
    float num    = startT[s_prev] + __shfl_sync(FULL_MASK, em0, s_prev, 8);

    // ---- Phase 1: t = 1..1016, all batches guaranteed active (lengths >= 1024) ----
    float emv[8]; int tgv[8];
    #pragma unroll
    for (int u = 0; u < 8; u++) {
        emv[u] = emb[(1 + u) * 8];
        tgv[u] = tgb[1 + u];
    }
    int t;
    for (t = 1; t + 15 <= 1016; t += 8) {
        float emn[8]; int tgn[8];
        #pragma unroll
        for (int u = 0; u < 8; u++) {            // double-buffer: prefetch next block
            emn[u] = emb[(t + 8 + u) * 8];
            tgn[u] = tgb[t + 8 + u];
        }
        #pragma unroll
        for (int u = 0; u < 8; u++)
            crf_step(emv[u], tgv[u], E, s_trans, j, true, a, num, s_prev);
        crf_renorm(a, c);
        #pragma unroll
        for (int u = 0; u < 8; u++) { emv[u] = emn[u]; tgv[u] = tgn[u]; }
    }
    // tail block of phase 1 (t == 1009..1016)
    #pragma unroll
    for (int u = 0; u < 8; u++)
        crf_step(emv[u], tgv[u], E, s_trans, j, true, a, num, s_prev);
    crf_renorm(a, c);
    t += 8;                                      // t == 1017

    // ---- Phase 2: t = 1017..2047, per-group early exit on tag==0 (mask is a prefix) ----
    bool act = true;
    for (; t < L_; t += 8) {
        float pem[8]; int ptg[8];
        #pragma unroll
        for (int u = 0; u < 8; u++) {
            int tt = t + u;
            bool ld = act && (tt < L_);
            pem[u] = ld ? emb[tt * 8] : 0.0f;
            ptg[u] = ld ? tgb[tt] : 0;
        }
        #pragma unroll
        for (int u = 0; u < 8; u++) {
            int tt = t + u;                      // warp-uniform
            if (tt < L_) {
                bool a2 = act && (ptg[u] != 0);
                crf_step(pem[u], ptg[u], E, s_trans, j, a2, a, num, s_prev);
                act = a2;
            }
        }
        crf_renorm(a, c);                        // invariant-preserving even when frozen
        if (!__ballot_sync(FULL_MASK, act)) break;
    }

    // ---- Finalize: denom = ln2 * (c + log2( sum_j a_j * exp(end_j) )) ----
    float vend = a * exp2f(endT[j] * LOG2E_F);
    vend += __shfl_xor_sync(FULL_MASK, vend, 1);
    vend += __shfl_xor_sync(FULL_MASK, vend, 2);
    vend += __shfl_xor_sync(FULL_MASK, vend, 4);
    float denom = (c + log2f(vend)) * LN2_F;
    num += endT[s_prev];
    if (j == 0) g_llh[b] = num - denom;
}

__global__ void crf_reduce(float* __restrict__ out)
{
    __shared__ float sm[256];
    int tid = threadIdx.x;
    float s = 0.0f;
    for (int i = tid; i < B_; i += 256) s += g_llh[i];
    sm[tid] = s;
    __syncthreads();
    for (int k = 128; k > 0; k >>= 1) {
        if (tid < k) sm[tid] += sm[tid + k];
        __syncthreads();
    }
    if (tid == 0) out[0] = -sm[0] * (1.0f / (float)B_);
}

extern "C" void kernel_launch(void* const* d_in, const int* in_sizes, int n_in,
                              void* d_out, int out_size)
{
    const float* em    = (const float*)d_in[0];   // (B, L, T) f32
    const float* trans = (const float*)d_in[1];   // (T, T)    f32
    const float* st    = (const float*)d_in[2];   // (T,)      f32
    const float* en    = (const float*)d_in[3];   // (T,)      f32
    const int*   tags  = (const int*)  d_in[4];   // (B, L)    int32

    crf_main<<<256, 64>>>(em, trans, st, en, tags);   // 512 warps, 4 batches/warp
    crf_reduce<<<1, 256>>>((float*)d_out);
}